// round 2
// baseline (speedup 1.0000x reference)
#include <cuda_runtime.h>
#include <math.h>

#define TSIG (1 << 20)
#define KM 3
#define ALPHA_C 2000.0f
#define TAU_C 1e-7f
#define TAU2F 1e-14f
#define TOL_C 1e-6
#define NITER 50
#define NB_ITER 1184
#define SPITCH 1028
#define SMEM_FFT ((8 * SPITCH + 512) * (int)sizeof(float2))

// Scratch (sanctioned __device__ globals):
// [0,T)    : F (forward FFT of x); later reused as FFT work buffer B for inverse
// [T,2T)   : lam buffer 0
// [2T,3T)  : lam buffer 1          (lam1/lam2 also reused as part of work B)
// [3T,6T)  : forward work / final conj(u) (3 modes)
__device__ float2 g_buf[6 * (size_t)TSIG];
__device__ float  g_part[NB_ITER * 8];
__device__ float  g_omega[2][KM];
__device__ int    g_done;
__device__ int    g_fp;

__device__ __forceinline__ float2 cmulf(float2 a, float2 b) {
    return make_float2(a.x * b.x - a.y * b.y, a.x * b.y + a.y * b.x);
}

__device__ __forceinline__ float warp_red(float v) {
    #pragma unroll
    for (int o = 16; o; o >>= 1) v += __shfl_down_sync(0xffffffffu, v, o);
    return v;
}

// ---------------------------------------------------------------------------
// Four-step FFT, N = 1024 x 1024.  Stockham radix-2 DIF in shared memory,
// 4 sub-FFTs (columns) per block, 256 threads, shared W_1024 twiddle table.
// ---------------------------------------------------------------------------

__device__ __forceinline__ void fft1024_shared(float2*& src, float2*& dst,
                                               const float2* tw, int t) {
    #pragma unroll 1
    for (int s = 0; s < 10; s++) {
        int r = 1 << s;
        #pragma unroll
        for (int u = 0; u < 8; u++) {
            int id = u * 256 + t;          // 0..2047
            int c  = id >> 9;              // column 0..3
            int bf = id & 511;             // butterfly 0..511
            int j  = bf >> s;
            float2 a = src[c * SPITCH + bf];
            float2 b = src[c * SPITCH + bf + 512];
            float2 w = tw[j << s];         // W_1024^(j<<s) = W_{2l}^j
            int o = bf + ((bf >> s) << s); // k + 2*r*j
            dst[c * SPITCH + o]     = make_float2(a.x + b.x, a.y + b.y);
            float2 d = make_float2(a.x - b.x, a.y - b.y);
            dst[c * SPITCH + o + r] = cmulf(d, w);
        }
        __syncthreads();
        float2* tmp = src; src = dst; dst = tmp;
    }
}

template <int REAL_IN>
__global__ void __launch_bounds__(256) fft_pass1(const float* rin, const float2* cin,
                                                 float2* out) {
    extern __shared__ float2 sh[];
    float2* bufA = sh;
    float2* bufB = sh + 4 * SPITCH;
    float2* tw   = sh + 8 * SPITCH;
    const int t   = threadIdx.x;
    const int n2b = blockIdx.x * 4;
    const int b   = blockIdx.y;

    for (int m = t; m < 512; m += 256) {
        double sd, cd;
        sincospi(-(double)m * (1.0 / 512.0), &sd, &cd);   // exp(-2pi i m/1024)
        tw[m] = make_float2((float)cd, (float)sd);
    }
    for (int i = t; i < 4096; i += 256) {
        int n1 = i >> 2, c = i & 3;
        float2 v;
        if (REAL_IN) v = make_float2(rin[(n1 << 10) + n2b + c], 0.0f);
        else         v = cin[(size_t)b * TSIG + (n1 << 10) + n2b + c];
        bufA[c * SPITCH + n1] = v;
    }
    __syncthreads();

    float2 *src = bufA, *dst = bufB;
    fft1024_shared(src, dst, tw, t);

    // multiply by W_N^(n2*k1), store A[k1*1024 + n2]
    for (int i = t; i < 4096; i += 256) {
        int k1 = i >> 2, c = i & 3;
        int n2 = n2b + c;
        long long m = ((long long)n2 * (long long)k1) & (long long)(TSIG - 1);
        double sd, cd;
        sincospi(-2.0 * (double)m * (1.0 / (double)TSIG), &sd, &cd);
        float2 v = src[c * SPITCH + k1];
        out[(size_t)b * TSIG + ((size_t)k1 << 10) + n2] =
            cmulf(v, make_float2((float)cd, (float)sd));
    }
}

template <int REAL_OUT>
__global__ void __launch_bounds__(256) fft_pass2(const float2* in, float2* cout,
                                                 float* rout) {
    extern __shared__ float2 sh[];
    float2* bufA = sh;
    float2* bufB = sh + 4 * SPITCH;
    float2* tw   = sh + 8 * SPITCH;
    const int t   = threadIdx.x;
    const int k1b = blockIdx.x * 4;
    const int b   = blockIdx.y;

    for (int m = t; m < 512; m += 256) {
        double sd, cd;
        sincospi(-(double)m * (1.0 / 512.0), &sd, &cd);
        tw[m] = make_float2((float)cd, (float)sd);
    }
    for (int i = t; i < 4096; i += 256) {
        int c = i >> 10, n2 = i & 1023;
        bufA[c * SPITCH + n2] = in[(size_t)b * TSIG + ((size_t)(k1b + c) << 10) + n2];
    }
    __syncthreads();

    float2 *src = bufA, *dst = bufB;
    fft1024_shared(src, dst, tw, t);

    const float invT = 1.0f / (float)TSIG;
    for (int i = t; i < 4096; i += 256) {
        int k2 = i >> 2, c = i & 3;
        float2 v = src[c * SPITCH + k2];
        size_t o = (size_t)b * TSIG + ((size_t)k2 << 10) + k1b + c;
        if (REAL_OUT) rout[o] = v.x * invT;
        else          cout[o] = v;
    }
}

// ---------------------------------------------------------------------------
// VMD iteration kernels
// ---------------------------------------------------------------------------

__global__ void vmd_init(const float* om_init) {
    int idx = blockIdx.x * blockDim.x + threadIdx.x;
    if (idx < KM) g_omega[0][idx] = om_init[idx];
    if (idx == 0) { g_done = 0; g_fp = 1; }
    int stride = gridDim.x * blockDim.x;
    for (int j = idx; j < TSIG; j += stride)
        g_buf[(size_t)TSIG + j] = make_float2(0.0f, 0.0f);
}

__global__ void __launch_bounds__(256) vmd_iter(int n, int do_check) {
    if (g_done) return;
    const int pi = n & 1, po = pi ^ 1;
    const float2* __restrict__ F      = g_buf;
    const float2* __restrict__ lam_in = g_buf + (size_t)TSIG * (1 + pi);
    float2*       __restrict__ lam_out = g_buf + (size_t)TSIG * (1 + po);
    const float w0 = g_omega[pi][0], w1 = g_omega[pi][1], w2 = g_omega[pi][2];
    float p0 = 0.f, p1 = 0.f, p2 = 0.f;
    if (do_check) { p0 = g_omega[po][0]; p1 = g_omega[po][1]; p2 = g_omega[po][2]; }

    float s0a = 0, s0b = 0, s0c = 0, s1a = 0, s1b = 0, s1c = 0, dsq = 0, psq = 0;
    const float invT = 1.0f / (float)TSIG;
    int tid = blockIdx.x * blockDim.x + threadIdx.x;
    int stride = gridDim.x * blockDim.x;

    for (int j = tid; j < TSIG; j += stride) {
        float f = (float)j * invT;
        if (j >= TSIG / 2) f -= 1.0f;
        float2 Fv = F[j];
        float2 Lv = lam_in[j];
        float rr = Fv.x - 0.5f * Lv.x;
        float ri = Fv.y - 0.5f * Lv.y;
        float d0 = f - w0, d1 = f - w1, d2 = f - w2;
        float b0 = d0 * d0, b1 = d1 * d1, b2 = d2 * d2;
        float i0 = 1.0f / (1.0f + ALPHA_C * (b0 + b1 + TAU2F));
        float i1 = 1.0f / (1.0f + ALPHA_C * (b0 + b1 + b2 + TAU2F));
        float i2 = 1.0f / (1.0f + ALPHA_C * (b1 + b2 + TAU2F));
        float mag = rr * rr + ri * ri;
        float pw0 = mag * i0 * i0, pw1 = mag * i1 * i1, pw2 = mag * i2 * i2;
        s0a += pw0; s0b += pw1; s0c += pw2;
        s1a += f * pw0; s1b += f * pw1; s1c += f * pw2;
        float isum = i0 + i1 + i2;
        float2 Lold;
        if (do_check) Lold = lam_out[j];       // L_{n-1}, read before overwrite
        lam_out[j] = make_float2(Lv.x + TAU_C * (rr * isum - Fv.x),
                                 Lv.y + TAU_C * (ri * isum - Fv.y));
        if (do_check) {
            float qr = Fv.x - 0.5f * Lold.x;
            float qi = Fv.y - 0.5f * Lold.y;
            float e0 = f - p0, e1 = f - p1, e2 = f - p2;
            float c0 = e0 * e0, c1 = e1 * e1, c2 = e2 * e2;
            float h0 = 1.0f / (1.0f + ALPHA_C * (c0 + c1 + TAU2F));
            float h1 = 1.0f / (1.0f + ALPHA_C * (c0 + c1 + c2 + TAU2F));
            float h2 = 1.0f / (1.0f + ALPHA_C * (c1 + c2 + TAU2F));
            float qmag = qr * qr + qi * qi;
            psq += qmag * (h0 * h0 + h1 * h1 + h2 * h2);
            float xr, xi;
            xr = rr * i0 - qr * h0; xi = ri * i0 - qi * h0; dsq += xr * xr + xi * xi;
            xr = rr * i1 - qr * h1; xi = ri * i1 - qi * h1; dsq += xr * xr + xi * xi;
            xr = rr * i2 - qr * h2; xi = ri * i2 - qi * h2; dsq += xr * xr + xi * xi;
        }
    }

    float acc[8] = { s0a, s0b, s0c, s1a, s1b, s1c, dsq, psq };
    __shared__ float sred[8][8];
    int lane = threadIdx.x & 31, warp = threadIdx.x >> 5;
    #pragma unroll
    for (int a = 0; a < 8; a++) {
        float v = warp_red(acc[a]);
        if (lane == 0) sred[warp][a] = v;
    }
    __syncthreads();
    if (threadIdx.x < 8) {
        int a = threadIdx.x;
        float s = 0;
        #pragma unroll
        for (int w = 0; w < 8; w++) s += sred[w][a];
        g_part[blockIdx.x * 8 + a] = s;
    }
}

__global__ void vmd_finalize(int n, int do_check) {
    if (g_done) return;
    int t = threadIdx.x;
    double loc[8] = {0, 0, 0, 0, 0, 0, 0, 0};
    for (int b = t; b < NB_ITER; b += 256) {
        #pragma unroll
        for (int a = 0; a < 8; a++) loc[a] += (double)g_part[b * 8 + a];
    }
    __shared__ double sred[8][8];
    int lane = t & 31, warp = t >> 5;
    #pragma unroll
    for (int a = 0; a < 8; a++) {
        double v = loc[a];
        #pragma unroll
        for (int o = 16; o; o >>= 1) v += __shfl_down_sync(0xffffffffu, v, o);
        if (lane == 0) sred[warp][a] = v;
    }
    __syncthreads();
    if (t == 0) {
        double s[8];
        #pragma unroll
        for (int a = 0; a < 8; a++) {
            double v = 0;
            for (int w = 0; w < 8; w++) v += sred[w][a];
            s[a] = v;
        }
        double wn0 = s[3] / s[0], wn1 = s[4] / s[1], wn2 = s[5] / s[2];
        int po = (n + 1) & 1;
        g_omega[po][0] = (float)wn0;
        g_omega[po][1] = (float)wn1;
        g_omega[po][2] = (float)wn2;
        if (do_check) {
            double udiff = s[6] / s[7];
            double omd = (fabs(wn0 - wn2) + fabs(wn1 - wn0) + fabs(wn2 - wn1)) * (1.0 / 3.0);
            if (udiff < TOL_C && omd < TOL_C) { g_done = 1; g_fp = n & 1; }
        }
    }
}

// Final u_hat (from frozen/last state), conjugated for the ifft-via-fft trick.
__global__ void __launch_bounds__(256) vmd_final_u() {
    int fp = g_fp;
    const float2* __restrict__ F   = g_buf;
    const float2* __restrict__ lam = g_buf + (size_t)TSIG * (1 + fp);
    const float w0 = g_omega[fp][0], w1 = g_omega[fp][1], w2 = g_omega[fp][2];
    float2* __restrict__ U = g_buf + (size_t)3 * TSIG;
    const float invT = 1.0f / (float)TSIG;
    int tid = blockIdx.x * blockDim.x + threadIdx.x;
    int stride = gridDim.x * blockDim.x;
    for (int j = tid; j < TSIG; j += stride) {
        float f = (float)j * invT;
        if (j >= TSIG / 2) f -= 1.0f;
        float2 Fv = F[j];
        float2 Lv = lam[j];
        float rr = Fv.x - 0.5f * Lv.x;
        float ri = Fv.y - 0.5f * Lv.y;
        float d0 = f - w0, d1 = f - w1, d2 = f - w2;
        float b0 = d0 * d0, b1 = d1 * d1, b2 = d2 * d2;
        float i0 = 1.0f / (1.0f + ALPHA_C * (b0 + b1 + TAU2F));
        float i1 = 1.0f / (1.0f + ALPHA_C * (b0 + b1 + b2 + TAU2F));
        float i2 = 1.0f / (1.0f + ALPHA_C * (b1 + b2 + TAU2F));
        U[j]                    = make_float2(rr * i0, -ri * i0);
        U[(size_t)TSIG + j]     = make_float2(rr * i1, -ri * i1);
        U[(size_t)2 * TSIG + j] = make_float2(rr * i2, -ri * i2);
    }
}

// ---------------------------------------------------------------------------

extern "C" void kernel_launch(void* const* d_in, const int* in_sizes, int n_in,
                              void* d_out, int out_size) {
    const float* x       = (const float*)d_in[0];
    const float* om_init = (const float*)d_in[1];
    float* out = (float*)d_out;

    cudaFuncSetAttribute(fft_pass1<1>, cudaFuncAttributeMaxDynamicSharedMemorySize, SMEM_FFT);
    cudaFuncSetAttribute(fft_pass1<0>, cudaFuncAttributeMaxDynamicSharedMemorySize, SMEM_FFT);
    cudaFuncSetAttribute(fft_pass2<0>, cudaFuncAttributeMaxDynamicSharedMemorySize, SMEM_FFT);
    cudaFuncSetAttribute(fft_pass2<1>, cudaFuncAttributeMaxDynamicSharedMemorySize, SMEM_FFT);

    float2* buf;
    cudaGetSymbolAddress((void**)&buf, g_buf);
    float2* F   = buf;                       // [0, T)
    float2* wa  = buf + (size_t)3 * TSIG;    // forward work / final conj(u)
    float2* wb  = buf;                       // inverse work B overlays F+lam (dead then)

    // Forward FFT of x -> F
    fft_pass1<1><<<dim3(256, 1), 256, SMEM_FFT>>>(x, nullptr, wa);
    fft_pass2<0><<<dim3(256, 1), 256, SMEM_FFT>>>(wa, F, nullptr);

    vmd_init<<<512, 256>>>(om_init);

    for (int n = 0; n < NITER; n++) {
        int dc = (n % 10 == 0 && n > 0) ? 1 : 0;
        vmd_iter<<<NB_ITER, 256>>>(n, dc);
        vmd_finalize<<<1, 256>>>(n, dc);
    }

    vmd_final_u<<<NB_ITER, 256>>>();

    // ifft(u) real part = Re(fft(conj(u)))/T, batched over K=3
    fft_pass1<0><<<dim3(256, 3), 256, SMEM_FFT>>>(nullptr, wa, wb);
    fft_pass2<1><<<dim3(256, 3), 256, SMEM_FFT>>>(wb, nullptr, out);
}